// round 15
// baseline (speedup 1.0000x reference)
#include <cuda_runtime.h>
#include <cuda_bf16.h>
#include <cstdint>

// ---------------------------------------------------------------------------
// Problem constants: x [B=2, S=2048, d=1024], H=16, Dh=64, causal MHA, fp32.
// ---------------------------------------------------------------------------
#define D_MODEL 1024
#define NUM_HEADS 16
#define D_HEAD 64
#define SEQ_LEN 2048
#define BATCH 2
#define M_ROWS (BATCH * SEQ_LEN)   // 4096
#define NT64 (SEQ_LEN / 64)        // 32 key tiles (64 keys) per (b,h)
#define STAGE_WORDS 8192           // 32KB per tile: [Khi tf32 4096][V bf16 h/l 4096]
#define GW 8192                    // gemm stage words
#define KT_N 32                    // k-tiles per GEMM
#define WSTRIDE ((size_t)8 * KT_N * 4096)
#define LOG2E 1.4426950408889634f

// Scratch (alloc-free rule: __device__ globals).
__device__ float    g_Q[M_ROWS * D_MODEL];
__device__ uint32_t g_APK[(size_t)(M_ROWS / 128) * KT_N * 4096];
__device__ uint32_t g_WPK[4 * WSTRIDE];
__device__ uint32_t g_KVP[(size_t)BATCH * NUM_HEADS * NT64 * STAGE_WORDS];

__device__ __forceinline__ uint32_t f2tf32(float x) {
    uint32_t r;
    asm("cvt.rna.tf32.f32 %0, %1;" : "=r"(r) : "f"(x));
    return r;
}
__device__ __forceinline__ float ex2f(float x) {
    float r;
    asm("ex2.approx.f32 %0, %1;" : "=f"(r) : "f"(x));
    return r;
}
// Pack two f32 -> bf16x2 (hi arg -> upper half, lo arg -> lower half).
__device__ __forceinline__ uint32_t cvtbf2(float hi, float lo) {
    uint32_t r;
    asm("cvt.rn.bf16x2.f32 %0, %1, %2;" : "=r"(r) : "f"(hi), "f"(lo));
    return r;
}
__device__ __forceinline__ float bflo(uint32_t p) { return __uint_as_float(p << 16); }
__device__ __forceinline__ float bfhi(uint32_t p) { return __uint_as_float(p & 0xFFFF0000u); }

__device__ __forceinline__ void mma_tf32(float c[4], const uint32_t a[4],
                                         uint32_t b0, uint32_t b1) {
    asm volatile(
        "mma.sync.aligned.m16n8k8.row.col.f32.tf32.tf32.f32 "
        "{%0,%1,%2,%3}, {%4,%5,%6,%7}, {%8,%9}, {%0,%1,%2,%3};\n"
        : "+f"(c[0]), "+f"(c[1]), "+f"(c[2]), "+f"(c[3])
        : "r"(a[0]), "r"(a[1]), "r"(a[2]), "r"(a[3]), "r"(b0), "r"(b1));
}
__device__ __forceinline__ void mma_bf16(float c[4], const uint32_t a[4],
                                         uint32_t b0, uint32_t b1) {
    asm volatile(
        "mma.sync.aligned.m16n8k16.row.col.f32.bf16.bf16.f32 "
        "{%0,%1,%2,%3}, {%4,%5,%6,%7}, {%8,%9}, {%0,%1,%2,%3};\n"
        : "+f"(c[0]), "+f"(c[1]), "+f"(c[2]), "+f"(c[3])
        : "r"(a[0]), "r"(a[1]), "r"(a[2]), "r"(a[3]), "r"(b0), "r"(b1));
}

// ---------------------------------------------------------------------------
// pack_a: A [M_ROWS][D_MODEL] fp32 -> frag-order tf32 (x only).
// ---------------------------------------------------------------------------
__global__ __launch_bounds__(256) void pack_a_kernel(
    const float* __restrict__ A, uint32_t* __restrict__ out)
{
    __shared__ float s[128][36];
    const int kt = blockIdx.x;
    const int rb = blockIdx.y;
    const int tid = threadIdx.x;

    #pragma unroll
    for (int i = 0; i < 4; i++) {
        int idx = tid + i * 256;
        int row = idx >> 3;
        int c4  = idx & 7;
        float4 v = *reinterpret_cast<const float4*>(
            A + (size_t)(rb * 128 + row) * D_MODEL + kt * 32 + c4 * 4);
        *reinterpret_cast<float4*>(&s[row][c4 * 4]) = v;
    }
    __syncthreads();

    const int lane = tid & 31;
    const int lrow = lane >> 2, lcol = lane & 3;
    uint32_t* blk = out + ((size_t)rb * KT_N + kt) * 4096;
    #pragma unroll
    for (int i = 0; i < 4; i++) {
        int combo = (tid >> 5) + i * 8;
        int kat = combo >> 3, mt = combo & 7;
        int m0 = mt * 16, kk = kat * 8;
        uint4 w;
        w.x = f2tf32(s[m0 + lrow    ][kk + lcol    ]);
        w.y = f2tf32(s[m0 + 8 + lrow][kk + lcol    ]);
        w.z = f2tf32(s[m0 + lrow    ][kk + lcol + 4]);
        w.w = f2tf32(s[m0 + 8 + lrow][kk + lcol + 4]);
        *reinterpret_cast<uint4*>(blk + (size_t)(combo * 32 + lane) * 4) = w;
    }
}

// ---------------------------------------------------------------------------
// pack_w: W [K][N] fp32 (4 matrices) -> frag-order tf32.
// ---------------------------------------------------------------------------
__global__ __launch_bounds__(256) void pack_w_kernel(
    const float* __restrict__ w0, const float* __restrict__ w1,
    const float* __restrict__ w2, const float* __restrict__ w3,
    uint32_t* __restrict__ out)
{
    __shared__ float s[32][132];
    const float* srcs[4] = {w0, w1, w2, w3};
    const int kt  = blockIdx.x;
    const int cb  = blockIdx.y;
    const int mat = blockIdx.z;
    const int tid = threadIdx.x;
    const float* W = srcs[mat];

    #pragma unroll
    for (int i = 0; i < 4; i++) {
        int idx = tid + i * 256;
        int row = idx >> 5;
        int c4  = idx & 31;
        float4 v = *reinterpret_cast<const float4*>(
            W + (size_t)(kt * 32 + row) * D_MODEL + cb * 128 + c4 * 4);
        *reinterpret_cast<float4*>(&s[row][c4 * 4]) = v;
    }
    __syncthreads();

    const int lane = tid & 31;
    const int lrow = lane >> 2, lcol = lane & 3;
    uint32_t* blk = out + (((size_t)mat * 8 + cb) * KT_N + kt) * 4096;
    #pragma unroll
    for (int i = 0; i < 8; i++) {
        int combo = (tid >> 5) + i * 8;
        int kat = combo >> 4, nt = combo & 15;
        int kk = kat * 8, n0 = nt * 8;
        uint2 w;
        w.x = f2tf32(s[kk + lcol    ][n0 + lrow]);
        w.y = f2tf32(s[kk + lcol + 4][n0 + lrow]);
        *reinterpret_cast<uint2*>(blk + (size_t)(combo * 32 + lane) * 2) = w;
    }
}

// ---------------------------------------------------------------------------
// GEMM body. mode 0: fp32 row-major C. mode 1: K tf32 fragment layout.
// mode 2: V bf16 hi/lo fragment layout (16-bit element stores).
// V layout: uint4 per (nt2 0..3, nv 0..7, lane): .x=vh keys(2t,2t+1)@dh,
//   .y=vh keys(2t+8,2t+9), .z=vl(2t,2t+1), .w=vl(2t+8,2t+9); even key = low half.
// ---------------------------------------------------------------------------
__device__ __forceinline__ void gemm_body(
    const uint32_t* __restrict__ Asrc, const uint32_t* __restrict__ Bsrc,
    const float* __restrict__ bias, float* __restrict__ C,
    uint32_t* __restrict__ KVpk, int mode,
    uint32_t* gsm, int cb, int rb)
{
    const int tid  = threadIdx.x;
    const int lane = tid & 31;
    const int warp = tid >> 5;
    const int wmt = (warp & 3) * 2;
    const int wnt = (warp >> 2) * 8;
    const int lrow = lane >> 2;
    const int lcol = lane & 3;

    const uint32_t sm_addr = (uint32_t)__cvta_generic_to_shared(gsm);

    auto issue_stage = [&](int t) {
        if (t < KT_N) {
            uint32_t dst0 = sm_addr + ((t % 3) * GW) * 4;
            const uint32_t* sa = Asrc + (size_t)t * 4096;
            const uint32_t* sb = Bsrc + (size_t)t * 4096;
            #pragma unroll
            for (int c = 0; c < 4; c++) {
                uint32_t off16 = (c * 256 + tid) * 16;
                asm volatile("cp.async.cg.shared.global [%0], [%1], 16;\n"
                             :: "r"(dst0 + off16), "l"((const char*)sa + off16));
                asm volatile("cp.async.cg.shared.global [%0], [%1], 16;\n"
                             :: "r"(dst0 + 16384 + off16), "l"((const char*)sb + off16));
            }
        }
        asm volatile("cp.async.commit_group;\n");
    };

    float c[2][8][4];
    #pragma unroll
    for (int mi = 0; mi < 2; mi++)
        #pragma unroll
        for (int ni = 0; ni < 8; ni++)
            #pragma unroll
            for (int r = 0; r < 4; r++) c[mi][ni][r] = 0.0f;

    issue_stage(0);
    issue_stage(1);

    for (int t = 0; t < KT_N; t++) {
        asm volatile("cp.async.wait_group 1;\n");
        __syncthreads();

        const uint32_t* As = gsm + (t % 3) * GW;
        const uint32_t* Bs = As + 4096;

        #pragma unroll
        for (int kat = 0; kat < 4; kat++) {
            uint32_t a[2][4];
            #pragma unroll
            for (int mi = 0; mi < 2; mi++) {
                uint4 av = *reinterpret_cast<const uint4*>(
                    As + (size_t)(((kat * 8 + wmt + mi) * 32 + lane) * 4));
                a[mi][0] = av.x; a[mi][1] = av.y; a[mi][2] = av.z; a[mi][3] = av.w;
            }
            uint2 b[8];
            #pragma unroll
            for (int ni = 0; ni < 8; ni++)
                b[ni] = *reinterpret_cast<const uint2*>(
                    Bs + (size_t)(((kat * 16 + wnt + ni) * 32 + lane) * 2));
            #pragma unroll
            for (int mi = 0; mi < 2; mi++)
                #pragma unroll
                for (int ni = 0; ni < 8; ni++)
                    mma_tf32(c[mi][ni], a[mi], b[ni].x, b[ni].y);
        }

        issue_stage(t + 2);
    }

    if (mode == 0) {
        #pragma unroll
        for (int mi = 0; mi < 2; mi++) {
            int r0 = rb * 128 + (wmt + mi) * 16 + lrow;
            #pragma unroll
            for (int ni = 0; ni < 8; ni++) {
                int col = cb * 128 + (wnt + ni) * 8 + lcol * 2;
                float b0 = bias[col];
                float b1 = bias[col + 1];
                float2 v0 = make_float2(c[mi][ni][0] + b0, c[mi][ni][1] + b1);
                float2 v1 = make_float2(c[mi][ni][2] + b0, c[mi][ni][3] + b1);
                *reinterpret_cast<float2*>(C + (size_t)r0 * D_MODEL + col) = v0;
                *reinterpret_cast<float2*>(C + (size_t)(r0 + 8) * D_MODEL + col) = v1;
            }
        }
    } else if (mode == 1) {
        const int j0 = (lcol >> 1) + (lcol & 1) * 4;
        #pragma unroll
        for (int mi = 0; mi < 2; mi++) {
            #pragma unroll
            for (int ni = 0; ni < 8; ni++) {
                int colbase = cb * 128 + (wnt + ni) * 8 + lcol * 2;
                int h   = colbase >> 6;
                int dh0 = colbase & 63;
                int kd  = dh0 >> 3;
                float b0 = bias[colbase];
                float b1 = bias[colbase + 1];
                #pragma unroll
                for (int rr = 0; rr < 2; rr++) {
                    int r = rb * 128 + (wmt + mi) * 16 + lrow + rr * 8;
                    float v0 = c[mi][ni][rr * 2 + 0] + b0;
                    float v1 = c[mi][ni][rr * 2 + 1] + b1;
                    int b   = r >> 11;
                    int s   = r & 2047;
                    int key = s & 63;
                    uint32_t* blk = KVpk +
                        ((size_t)(b * 16 + h) * NT64 + (s >> 6)) * STAGE_WORDS;
                    uint32_t* d = blk + ((kd * 8 + (key >> 3)) * 64 + (key & 7) * 8);
                    d[j0]     = f2tf32(v0);
                    d[j0 + 2] = f2tf32(v1);
                }
            }
        }
    } else {
        // V: bf16 hi/lo fragment layout, 16-bit stores.
        #pragma unroll
        for (int mi = 0; mi < 2; mi++) {
            #pragma unroll
            for (int ni = 0; ni < 8; ni++) {
                int colbase = cb * 128 + (wnt + ni) * 8 + lcol * 2;
                int h   = colbase >> 6;
                int dh0 = colbase & 63;
                float b0 = bias[colbase];
                float b1 = bias[colbase + 1];
                #pragma unroll
                for (int rr = 0; rr < 2; rr++) {
                    int r = rb * 128 + (wmt + mi) * 16 + lrow + rr * 8;
                    float vv[2] = {c[mi][ni][rr * 2 + 0] + b0,
                                   c[mi][ni][rr * 2 + 1] + b1};
                    int b   = r >> 11;
                    int s   = r & 2047;
                    int key = s & 63;
                    uint32_t* blk = KVpk +
                        ((size_t)(b * 16 + h) * NT64 + (s >> 6)) * STAGE_WORDS;
                    int nt2  = key >> 4;
                    int kk   = key & 15;
                    int py   = kk >> 3;
                    int tt   = (kk >> 1) & 3;
                    int half = kk & 1;
                    #pragma unroll
                    for (int e = 0; e < 2; e++) {
                        int dh = dh0 + e;
                        int nv = dh >> 3, lr = dh & 7;
                        char* baseb = (char*)(blk + 4096 +
                            (size_t)(((nt2 * 8 + nv) * 32 + lr * 4 + tt) * 4));
                        __nv_bfloat16 bh = __float2bfloat16(vv[e]);
                        float hf = __bfloat162float(bh);
                        __nv_bfloat16 bl = __float2bfloat16(vv[e] - hf);
                        *(__nv_bfloat16*)(baseb + py * 4 + half * 2) = bh;
                        *(__nv_bfloat16*)(baseb + (2 + py) * 4 + half * 2) = bl;
                    }
                }
            }
        }
    }
}

__global__ __launch_bounds__(256) void gemm_qkv_kernel(
    const uint32_t* __restrict__ APK, const uint32_t* __restrict__ WPK,
    const float* __restrict__ bq, const float* __restrict__ bk,
    const float* __restrict__ bv,
    float* __restrict__ Q, uint32_t* __restrict__ KVpk)
{
    extern __shared__ __align__(16) uint32_t gsm[];
    const int cb = blockIdx.x, rb = blockIdx.y, z = blockIdx.z;
    const float* bias = (z == 0) ? bq : (z == 1) ? bk : bv;
    gemm_body(APK + (size_t)rb * KT_N * 4096,
              WPK + (size_t)z * WSTRIDE + (size_t)cb * KT_N * 4096,
              bias, Q, KVpk, z, gsm, cb, rb);
}

__global__ __launch_bounds__(256) void gemm_out_kernel(
    const uint32_t* __restrict__ APK, const uint32_t* __restrict__ BPK,
    const float* __restrict__ bias, float* __restrict__ C)
{
    extern __shared__ __align__(16) uint32_t gsm[];
    gemm_body(APK + (size_t)blockIdx.y * KT_N * 4096,
              BPK + (size_t)blockIdx.x * KT_N * 4096,
              bias, C, nullptr, 0, gsm, blockIdx.x, blockIdx.y);
}

// ---------------------------------------------------------------------------
// Tensor-core flash attention, BC=64; warp owns 32 queries (2 m-tiles).
// QK: tf32 1x (log2-domain scores). PV: bf16 hi/lo via m16n8k16 —
// C-fragment of S IS the A-fragment of PV: no shuffles.
// ---------------------------------------------------------------------------
__global__ __launch_bounds__(128, 2) void attn_mma_kernel(
    const float* __restrict__ Q, const uint32_t* __restrict__ KVP,
    uint32_t* __restrict__ APK)
{
    extern __shared__ __align__(16) uint32_t sm[];

    const int qt   = (int)gridDim.x - 1 - (int)blockIdx.x;
    const int bh   = blockIdx.y;
    const int b    = bh >> 4;
    const int h    = bh & 15;
    const int tid  = threadIdx.x;
    const int lane = tid & 31;
    const int warp = tid >> 5;
    const int g    = lane >> 2;
    const int t    = lane & 3;

    const int wq0 = qt * 128 + warp * 32;
    const size_t base = ((size_t)b * SEQ_LEN) * D_MODEL + h * D_HEAD;
    const uint32_t* tile_base = KVP + (size_t)bh * NT64 * STAGE_WORDS;
    const uint32_t sm_addr = (uint32_t)__cvta_generic_to_shared(sm);
    const int nkt = 2 * qt + 2;
    const float qscale = 0.125f * LOG2E;   // scores in log2 domain

    uint32_t qh[2][8][4];
    #pragma unroll
    for (int mi = 0; mi < 2; mi++) {
        const int row0 = wq0 + mi * 16 + g, row1 = row0 + 8;
        #pragma unroll
        for (int kd = 0; kd < 8; kd++) {
            int c0 = kd * 8 + t, c1 = c0 + 4;
            qh[mi][kd][0] = f2tf32(Q[base + (size_t)row0 * D_MODEL + c0] * qscale);
            qh[mi][kd][1] = f2tf32(Q[base + (size_t)row1 * D_MODEL + c0] * qscale);
            qh[mi][kd][2] = f2tf32(Q[base + (size_t)row0 * D_MODEL + c1] * qscale);
            qh[mi][kd][3] = f2tf32(Q[base + (size_t)row1 * D_MODEL + c1] * qscale);
        }
    }

    float oc[2][8][4];
    #pragma unroll
    for (int mi = 0; mi < 2; mi++)
        #pragma unroll
        for (int nv = 0; nv < 8; nv++)
            #pragma unroll
            for (int r = 0; r < 4; r++) oc[mi][nv][r] = 0.0f;

    float mm[2][2], ll[2][2];
    #pragma unroll
    for (int mi = 0; mi < 2; mi++) {
        mm[mi][0] = -1.0e30f; mm[mi][1] = -1.0e30f;
        ll[mi][0] = 0.0f;     ll[mi][1] = 0.0f;
    }

    auto issue_tile = [&](int kt) {
        if (kt < nkt) {
            const uint32_t* src = tile_base + (size_t)kt * STAGE_WORDS + tid * 4;
            uint32_t dst = sm_addr + ((kt % 3) * STAGE_WORDS + tid * 4) * 4;
            #pragma unroll
            for (int c = 0; c < 16; c++) {
                asm volatile("cp.async.cg.shared.global [%0], [%1], 16;\n"
                             :: "r"(dst + c * 2048), "l"(src + c * 512));
            }
        }
        asm volatile("cp.async.commit_group;\n");
    };

    issue_tile(0);
    issue_tile(1);

    for (int kt = 0; kt < nkt; kt++) {
        asm volatile("cp.async.wait_group 1;\n");
        __syncthreads();

        const uint32_t* stg = sm + (kt % 3) * STAGE_WORDS;
        const uint2* KhiS = reinterpret_cast<const uint2*>(stg);
        const uint4* VS4  = reinterpret_cast<const uint4*>(stg + 4096);
        const int k0 = kt * 64;

        if (k0 <= wq0 + 31) {
            // ---- S = QK^T (tf32, log2 domain) ----
            float sc[2][8][4];
            #pragma unroll
            for (int mi = 0; mi < 2; mi++)
                #pragma unroll
                for (int nt = 0; nt < 8; nt++)
                    #pragma unroll
                    for (int r = 0; r < 4; r++) sc[mi][nt][r] = 0.0f;

            #pragma unroll
            for (int kd = 0; kd < 8; kd++) {
                #pragma unroll
                for (int nt = 0; nt < 8; nt++) {
                    uint2 bh2 = KhiS[(kd * 8 + nt) * 32 + lane];
                    mma_tf32(sc[0][nt], qh[0][kd], bh2.x, bh2.y);
                    mma_tf32(sc[1][nt], qh[1][kd], bh2.x, bh2.y);
                }
            }

            // ---- causal mask ----
            if (k0 + 63 > wq0) {
                #pragma unroll
                for (int mi = 0; mi < 2; mi++) {
                    const int row0 = wq0 + mi * 16 + g, row1 = row0 + 8;
                    #pragma unroll
                    for (int nt = 0; nt < 8; nt++) {
                        int col = k0 + nt * 8 + 2 * t;
                        if (col     > row0) sc[mi][nt][0] = -1.0e30f;
                        if (col + 1 > row0) sc[mi][nt][1] = -1.0e30f;
                        if (col     > row1) sc[mi][nt][2] = -1.0e30f;
                        if (col + 1 > row1) sc[mi][nt][3] = -1.0e30f;
                    }
                }
            }

            // ---- online softmax: max + rescale (log2 domain) ----
            #pragma unroll
            for (int mi = 0; mi < 2; mi++) {
                float mt0 = sc[mi][0][0], mt1 = sc[mi][0][2];
                #pragma unroll
                for (int nt = 0; nt < 8; nt++) {
                    mt0 = fmaxf(mt0, fmaxf(sc[mi][nt][0], sc[mi][nt][1]));
                    mt1 = fmaxf(mt1, fmaxf(sc[mi][nt][2], sc[mi][nt][3]));
                }
                #pragma unroll
                for (int w = 1; w < 4; w <<= 1) {
                    mt0 = fmaxf(mt0, __shfl_xor_sync(0xffffffff, mt0, w));
                    mt1 = fmaxf(mt1, __shfl_xor_sync(0xffffffff, mt1, w));
                }
                float mn0 = fmaxf(mm[mi][0], mt0), mn1 = fmaxf(mm[mi][1], mt1);
                float cr0 = ex2f(mm[mi][0] - mn0), cr1 = ex2f(mm[mi][1] - mn1);
                mm[mi][0] = mn0; mm[mi][1] = mn1;
                ll[mi][0] *= cr0; ll[mi][1] *= cr1;
                #pragma unroll
                for (int nv = 0; nv < 8; nv++) {
                    oc[mi][nv][0] *= cr0; oc[mi][nv][1] *= cr0;
                    oc[mi][nv][2] *= cr1; oc[mi][nv][3] *= cr1;
                }
            }

            // ---- phase 1: p = 2^(s-m), accumulate l, p stays in sc ----
            #pragma unroll
            for (int mi = 0; mi < 2; mi++) {
                #pragma unroll
                for (int nt = 0; nt < 8; nt++) {
                    sc[mi][nt][0] = ex2f(sc[mi][nt][0] - mm[mi][0]);
                    sc[mi][nt][1] = ex2f(sc[mi][nt][1] - mm[mi][0]);
                    sc[mi][nt][2] = ex2f(sc[mi][nt][2] - mm[mi][1]);
                    sc[mi][nt][3] = ex2f(sc[mi][nt][3] - mm[mi][1]);
                    ll[mi][0] += sc[mi][nt][0] + sc[mi][nt][1];
                    ll[mi][1] += sc[mi][nt][2] + sc[mi][nt][3];
                }
            }

            // ---- phase 2: PV via bf16 m16n8k16, C-frag == A-frag ----
            #pragma unroll
            for (int nt2 = 0; nt2 < 4; nt2++) {
                uint32_t aH[2][4], aL[2][4];
                #pragma unroll
                for (int mi = 0; mi < 2; mi++) {
                    const float* pA = sc[mi][2 * nt2];
                    const float* pB = sc[mi][2 * nt2 + 1];
                    aH[mi][0] = cvtbf2(pA[1], pA[0]);
                    aH[mi][1] = cvtbf2(pA[3], pA[2]);
                    aH[mi][2] = cvtbf2(pB[1], pB[0]);
                    aH[mi][3] = cvtbf2(pB[3], pB[2]);
                    aL[mi][0] = cvtbf2(pA[1] - bfhi(aH[mi][0]), pA[0] - bflo(aH[mi][0]));
                    aL[mi][1] = cvtbf2(pA[3] - bfhi(aH[mi][1]), pA[2] - bflo(aH[mi][1]));
                    aL[mi][2] = cvtbf2(pB[1] - bfhi(aH[mi][2]), pB[0] - bflo(aH[mi][2]));
                    aL[mi][3] = cvtbf2(pB[3] - bfhi(aH[mi][3]), pB[2] - bflo(aH[mi][3]));
                }
                #pragma unroll
                for (int nv = 0; nv < 8; nv++) {
                    uint4 v4 = VS4[(nt2 * 8 + nv) * 32 + lane];
                    mma_bf16(oc[0][nv], aH[0], v4.x, v4.y);
                    mma_bf16(oc[1][nv], aH[1], v4.x, v4.y);
                    mma_bf16(oc[0][nv], aL[0], v4.x, v4.y);
                    mma_bf16(oc[1][nv], aL[1], v4.x, v4.y);
                    mma_bf16(oc[0][nv], aH[0], v4.z, v4.w);
                    mma_bf16(oc[1][nv], aH[1], v4.z, v4.w);
                }
            }
        }

        issue_tile(kt + 2);
    }

    // ---- finalize: normalize, transpose to A-frag order, store packed ----
    const int src0 = (lane & ~3) | (t >> 1);
    const int src1 = src0 + 2;
    const bool odd = (t & 1);
    #pragma unroll
    for (int mi = 0; mi < 2; mi++) {
        #pragma unroll
        for (int w = 1; w < 4; w <<= 1) {
            ll[mi][0] += __shfl_xor_sync(0xffffffff, ll[mi][0], w);
            ll[mi][1] += __shfl_xor_sync(0xffffffff, ll[mi][1], w);
        }
    }
    const int rb = b * (SEQ_LEN / 128) + qt;
    uint32_t* ablk0 = APK + ((size_t)rb * KT_N + h * 2) * 4096;

    #pragma unroll
    for (int mi = 0; mi < 2; mi++) {
        const float inv0 = 1.0f / ll[mi][0], inv1 = 1.0f / ll[mi][1];
        const int mt = warp * 2 + mi;
        #pragma unroll
        for (int nv = 0; nv < 8; nv++) {
            float p0 = oc[mi][nv][0] * inv0, p1 = oc[mi][nv][1] * inv0;
            float p2 = oc[mi][nv][2] * inv1, p3 = oc[mi][nv][3] * inv1;
            float t00 = __shfl_sync(0xffffffff, p0, src0);
            float t01 = __shfl_sync(0xffffffff, p1, src0);
            float a0 = odd ? t01 : t00;
            float t10 = __shfl_sync(0xffffffff, p2, src0);
            float t11 = __shfl_sync(0xffffffff, p3, src0);
            float a1 = odd ? t11 : t10;
            float t20 = __shfl_sync(0xffffffff, p0, src1);
            float t21 = __shfl_sync(0xffffffff, p1, src1);
            float a2 = odd ? t21 : t20;
            float t30 = __shfl_sync(0xffffffff, p2, src1);
            float t31 = __shfl_sync(0xffffffff, p3, src1);
            float a3 = odd ? t31 : t30;
            uint4 wv = make_uint4(f2tf32(a0), f2tf32(a1), f2tf32(a2), f2tf32(a3));
            uint32_t* dst = ablk0 + (size_t)(nv >> 2) * 4096
                                  + (size_t)(((nv & 3) * 8 + mt) * 32 + lane) * 4;
            *reinterpret_cast<uint4*>(dst) = wv;
        }
    }
}

// ---------------------------------------------------------------------------
// Launch.
// ---------------------------------------------------------------------------
extern "C" void kernel_launch(void* const* d_in, const int* in_sizes, int n_in,
                              void* d_out, int out_size)
{
    const float* x  = (const float*)d_in[0];
    const float* Wq = (const float*)d_in[1];
    const float* bq = (const float*)d_in[2];
    const float* Wk = (const float*)d_in[3];
    const float* bk = (const float*)d_in[4];
    const float* Wv = (const float*)d_in[5];
    const float* bv = (const float*)d_in[6];
    const float* Wo = (const float*)d_in[7];
    const float* bo = (const float*)d_in[8];
    float* out = (float*)d_out;

    const int M = in_sizes[0] / D_MODEL;   // 4096
    const int B = M / SEQ_LEN;             // 2

    float* Qp;
    uint32_t *APKp, *WPKp, *KVPp;
    cudaGetSymbolAddress((void**)&Qp, g_Q);
    cudaGetSymbolAddress((void**)&APKp, g_APK);
    cudaGetSymbolAddress((void**)&WPKp, g_WPK);
    cudaGetSymbolAddress((void**)&KVPp, g_KVP);

    static bool attr_set = false;
    if (!attr_set) {
        cudaFuncSetAttribute(attn_mma_kernel,
                             cudaFuncAttributeMaxDynamicSharedMemorySize,
                             3 * STAGE_WORDS * 4);
        cudaFuncSetAttribute(gemm_qkv_kernel,
                             cudaFuncAttributeMaxDynamicSharedMemorySize,
                             3 * GW * 4);
        cudaFuncSetAttribute(gemm_out_kernel,
                             cudaFuncAttributeMaxDynamicSharedMemorySize,
                             3 * GW * 4);
        attr_set = true;
    }

    const int gemm_smem = 3 * GW * 4;
    dim3 qkv_grid(8, M / 128, 3);
    dim3 gemm_grid(8, M / 128);
    dim3 pa_grid(KT_N, M / 128);
    dim3 pw_grid(KT_N, 8, 4);

    pack_a_kernel<<<pa_grid, 256>>>(x, APKp);
    pack_w_kernel<<<pw_grid, 256>>>(Wq, Wk, Wv, Wo, WPKp);

    gemm_qkv_kernel<<<qkv_grid, 256, gemm_smem>>>(APKp, WPKp, bq, bk, bv, Qp, KVPp);

    dim3 attn_grid(SEQ_LEN / 128, B * NUM_HEADS);
    attn_mma_kernel<<<attn_grid, 128, 3 * STAGE_WORDS * 4>>>(Qp, KVPp, APKp);

    gemm_out_kernel<<<gemm_grid, 256, gemm_smem>>>(APKp, WPKp + 3 * WSTRIDE, bo, out);
}

// round 16
// speedup vs baseline: 1.0518x; 1.0518x over previous
#include <cuda_runtime.h>
#include <cstdint>

// ---------------------------------------------------------------------------
// Problem constants: x [B=2, S=2048, d=1024], H=16, Dh=64, causal MHA, fp32.
// ---------------------------------------------------------------------------
#define D_MODEL 1024
#define NUM_HEADS 16
#define D_HEAD 64
#define SEQ_LEN 2048
#define BATCH 2
#define M_ROWS (BATCH * SEQ_LEN)   // 4096
#define NT64 (SEQ_LEN / 64)        // 32 key tiles (64 keys) per (b,h)
#define STAGE_WORDS 8192           // attn: 32KB per tile [Khi 4096][Vhi 4096]
#define GW 8192                    // gemm stage words
#define KT_N 32                    // k-tiles per GEMM (K=1024 / 32)
#define WSTRIDE ((size_t)8 * KT_N * 4096)

// Scratch (alloc-free rule: __device__ globals).
__device__ float    g_Q[M_ROWS * D_MODEL];
__device__ uint32_t g_APK[(size_t)(M_ROWS / 128) * KT_N * 4096];      // A frag-packed
__device__ uint32_t g_WPK[4 * WSTRIDE];                               // W frag-packed
__device__ uint32_t g_KVP[(size_t)BATCH * NUM_HEADS * NT64 * STAGE_WORDS];

__device__ __forceinline__ uint32_t f2tf32(float x) {
    uint32_t r;
    asm("cvt.rna.tf32.f32 %0, %1;" : "=r"(r) : "f"(x));
    return r;
}

__device__ __forceinline__ void mma_tf32(float c[4], const uint32_t a[4],
                                         uint32_t b0, uint32_t b1) {
    asm volatile(
        "mma.sync.aligned.m16n8k8.row.col.f32.tf32.tf32.f32 "
        "{%0,%1,%2,%3}, {%4,%5,%6,%7}, {%8,%9}, {%0,%1,%2,%3};\n"
        : "+f"(c[0]), "+f"(c[1]), "+f"(c[2]), "+f"(c[3])
        : "r"(a[0]), "r"(a[1]), "r"(a[2]), "r"(a[3]), "r"(b0), "r"(b1));
}

// ---------------------------------------------------------------------------
// pack_a: A [M_ROWS][D_MODEL] fp32 -> frag-order tf32 (x only).
// ---------------------------------------------------------------------------
__global__ __launch_bounds__(256) void pack_a_kernel(
    const float* __restrict__ A, uint32_t* __restrict__ out)
{
    __shared__ float s[128][36];
    const int kt = blockIdx.x;
    const int rb = blockIdx.y;
    const int tid = threadIdx.x;

    #pragma unroll
    for (int i = 0; i < 4; i++) {
        int idx = tid + i * 256;
        int row = idx >> 3;
        int c4  = idx & 7;
        float4 v = *reinterpret_cast<const float4*>(
            A + (size_t)(rb * 128 + row) * D_MODEL + kt * 32 + c4 * 4);
        *reinterpret_cast<float4*>(&s[row][c4 * 4]) = v;
    }
    __syncthreads();

    const int lane = tid & 31;
    const int lrow = lane >> 2, lcol = lane & 3;
    uint32_t* blk = out + ((size_t)rb * KT_N + kt) * 4096;
    #pragma unroll
    for (int i = 0; i < 4; i++) {
        int combo = (tid >> 5) + i * 8;
        int kat = combo >> 3, mt = combo & 7;
        int m0 = mt * 16, kk = kat * 8;
        uint4 w;
        w.x = f2tf32(s[m0 + lrow    ][kk + lcol    ]);
        w.y = f2tf32(s[m0 + 8 + lrow][kk + lcol    ]);
        w.z = f2tf32(s[m0 + lrow    ][kk + lcol + 4]);
        w.w = f2tf32(s[m0 + 8 + lrow][kk + lcol + 4]);
        *reinterpret_cast<uint4*>(blk + (size_t)(combo * 32 + lane) * 4) = w;
    }
}

// ---------------------------------------------------------------------------
// pack_w: W [K][N] fp32 (4 matrices) -> frag-order tf32.
// ---------------------------------------------------------------------------
__global__ __launch_bounds__(256) void pack_w_kernel(
    const float* __restrict__ w0, const float* __restrict__ w1,
    const float* __restrict__ w2, const float* __restrict__ w3,
    uint32_t* __restrict__ out)
{
    __shared__ float s[32][132];
    const float* srcs[4] = {w0, w1, w2, w3};
    const int kt  = blockIdx.x;
    const int cb  = blockIdx.y;
    const int mat = blockIdx.z;
    const int tid = threadIdx.x;
    const float* W = srcs[mat];

    #pragma unroll
    for (int i = 0; i < 4; i++) {
        int idx = tid + i * 256;
        int row = idx >> 5;
        int c4  = idx & 31;
        float4 v = *reinterpret_cast<const float4*>(
            W + (size_t)(kt * 32 + row) * D_MODEL + cb * 128 + c4 * 4);
        *reinterpret_cast<float4*>(&s[row][c4 * 4]) = v;
    }
    __syncthreads();

    const int lane = tid & 31;
    const int lrow = lane >> 2, lcol = lane & 3;
    uint32_t* blk = out + (((size_t)mat * 8 + cb) * KT_N + kt) * 4096;
    #pragma unroll
    for (int i = 0; i < 8; i++) {
        int combo = (tid >> 5) + i * 8;
        int kat = combo >> 4, nt = combo & 15;
        int kk = kat * 8, n0 = nt * 8;
        uint2 w;
        w.x = f2tf32(s[kk + lcol    ][n0 + lrow]);
        w.y = f2tf32(s[kk + lcol + 4][n0 + lrow]);
        *reinterpret_cast<uint2*>(blk + (size_t)(combo * 32 + lane) * 2) = w;
    }
}

// ---------------------------------------------------------------------------
// GEMM body (R9 config, passing). mode 0: fp32 row-major C. mode 1/2: K/V
// written directly in packed 64-key fragment layout (bit-identical).
// ---------------------------------------------------------------------------
__device__ __forceinline__ void gemm_body(
    const uint32_t* __restrict__ Asrc, const uint32_t* __restrict__ Bsrc,
    const float* __restrict__ bias, float* __restrict__ C,
    uint32_t* __restrict__ KVpk, int mode,
    uint32_t* gsm, int cb, int rb)
{
    const int tid  = threadIdx.x;
    const int lane = tid & 31;
    const int warp = tid >> 5;
    const int wmt = (warp & 3) * 2;
    const int wnt = (warp >> 2) * 8;
    const int lrow = lane >> 2;
    const int lcol = lane & 3;

    const uint32_t sm_addr = (uint32_t)__cvta_generic_to_shared(gsm);

    auto issue_stage = [&](int t) {
        if (t < KT_N) {
            uint32_t dst0 = sm_addr + ((t % 3) * GW) * 4;
            const uint32_t* sa = Asrc + (size_t)t * 4096;
            const uint32_t* sb = Bsrc + (size_t)t * 4096;
            #pragma unroll
            for (int c = 0; c < 4; c++) {
                uint32_t off16 = (c * 256 + tid) * 16;
                asm volatile("cp.async.cg.shared.global [%0], [%1], 16;\n"
                             :: "r"(dst0 + off16), "l"((const char*)sa + off16));
                asm volatile("cp.async.cg.shared.global [%0], [%1], 16;\n"
                             :: "r"(dst0 + 16384 + off16), "l"((const char*)sb + off16));
            }
        }
        asm volatile("cp.async.commit_group;\n");
    };

    float c[2][8][4];
    #pragma unroll
    for (int mi = 0; mi < 2; mi++)
        #pragma unroll
        for (int ni = 0; ni < 8; ni++)
            #pragma unroll
            for (int r = 0; r < 4; r++) c[mi][ni][r] = 0.0f;

    issue_stage(0);
    issue_stage(1);

    for (int t = 0; t < KT_N; t++) {
        asm volatile("cp.async.wait_group 1;\n");
        __syncthreads();

        const uint32_t* As = gsm + (t % 3) * GW;
        const uint32_t* Bs = As + 4096;

        #pragma unroll
        for (int kat = 0; kat < 4; kat++) {
            uint32_t a[2][4];
            #pragma unroll
            for (int mi = 0; mi < 2; mi++) {
                uint4 av = *reinterpret_cast<const uint4*>(
                    As + (size_t)(((kat * 8 + wmt + mi) * 32 + lane) * 4));
                a[mi][0] = av.x; a[mi][1] = av.y; a[mi][2] = av.z; a[mi][3] = av.w;
            }
            uint2 b[8];
            #pragma unroll
            for (int ni = 0; ni < 8; ni++)
                b[ni] = *reinterpret_cast<const uint2*>(
                    Bs + (size_t)(((kat * 16 + wnt + ni) * 32 + lane) * 2));
            #pragma unroll
            for (int mi = 0; mi < 2; mi++)
                #pragma unroll
                for (int ni = 0; ni < 8; ni++)
                    mma_tf32(c[mi][ni], a[mi], b[ni].x, b[ni].y);
        }

        issue_stage(t + 2);
    }

    if (mode == 0) {
        #pragma unroll
        for (int mi = 0; mi < 2; mi++) {
            int r0 = rb * 128 + (wmt + mi) * 16 + lrow;
            #pragma unroll
            for (int ni = 0; ni < 8; ni++) {
                int col = cb * 128 + (wnt + ni) * 8 + lcol * 2;
                float b0 = bias[col];
                float b1 = bias[col + 1];
                float2 v0 = make_float2(c[mi][ni][0] + b0, c[mi][ni][1] + b1);
                float2 v1 = make_float2(c[mi][ni][2] + b0, c[mi][ni][3] + b1);
                *reinterpret_cast<float2*>(C + (size_t)r0 * D_MODEL + col) = v0;
                *reinterpret_cast<float2*>(C + (size_t)(r0 + 8) * D_MODEL + col) = v1;
            }
        }
    } else {
        const int j0 = (lcol >> 1) + (lcol & 1) * 4;
        #pragma unroll
        for (int mi = 0; mi < 2; mi++) {
            #pragma unroll
            for (int ni = 0; ni < 8; ni++) {
                int colbase = cb * 128 + (wnt + ni) * 8 + lcol * 2;
                int h   = colbase >> 6;
                int dh0 = colbase & 63;
                int kd  = dh0 >> 3;
                float b0 = bias[colbase];
                float b1 = bias[colbase + 1];
                #pragma unroll
                for (int rr = 0; rr < 2; rr++) {
                    int r = rb * 128 + (wmt + mi) * 16 + lrow + rr * 8;
                    float v0 = c[mi][ni][rr * 2 + 0] + b0;
                    float v1 = c[mi][ni][rr * 2 + 1] + b1;
                    int b   = r >> 11;
                    int s   = r & 2047;
                    int key = s & 63;
                    uint32_t* blk = KVpk +
                        ((size_t)(b * 16 + h) * NT64 + (s >> 6)) * STAGE_WORDS;
                    if (mode == 1) {
                        uint32_t* d = blk + ((kd * 8 + (key >> 3)) * 64 + (key & 7) * 8);
                        d[j0]     = f2tf32(v0);
                        d[j0 + 2] = f2tf32(v1);
                    } else {
                        int k7 = key & 7;
                        int jv = (k7 & 3) * 2 + (k7 >> 2);
                        uint32_t* d = blk + 4096 +
                            (((key >> 3) * 8 + kd) * 64 + (dh0 & 7) * 8) + jv;
                        d[0] = f2tf32(v0);
                        d[8] = f2tf32(v1);
                    }
                }
            }
        }
    }
}

__global__ __launch_bounds__(256) void gemm_qkv_kernel(
    const uint32_t* __restrict__ APK, const uint32_t* __restrict__ WPK,
    const float* __restrict__ bq, const float* __restrict__ bk,
    const float* __restrict__ bv,
    float* __restrict__ Q, uint32_t* __restrict__ KVpk)
{
    extern __shared__ __align__(16) uint32_t gsm[];
    const int cb = blockIdx.x, rb = blockIdx.y, z = blockIdx.z;
    const float* bias = (z == 0) ? bq : (z == 1) ? bk : bv;
    gemm_body(APK + (size_t)rb * KT_N * 4096,
              WPK + (size_t)z * WSTRIDE + (size_t)cb * KT_N * 4096,
              bias, Q, KVpk, z, gsm, cb, rb);
}

__global__ __launch_bounds__(256) void gemm_out_kernel(
    const uint32_t* __restrict__ APK, const uint32_t* __restrict__ BPK,
    const float* __restrict__ bias, float* __restrict__ C)
{
    extern __shared__ __align__(16) uint32_t gsm[];
    gemm_body(APK + (size_t)blockIdx.y * KT_N * 4096,
              BPK + (size_t)blockIdx.x * KT_N * 4096,
              bias, C, nullptr, 0, gsm, blockIdx.x, blockIdx.y);
}

// ---------------------------------------------------------------------------
// Tensor-core flash attention, BC=64; warp owns 32 queries (2 m-tiles).
// R13 math exactly; Q fragments live in SMEM (per-warp private region) to
// eliminate register spills. 2-stage KV pipeline (2 barriers/tile) + 32KB Q.
// ---------------------------------------------------------------------------
__global__ __launch_bounds__(128, 2) void attn_mma_kernel(
    const float* __restrict__ Q, const uint32_t* __restrict__ KVP,
    uint32_t* __restrict__ APK)
{
    extern __shared__ __align__(16) uint32_t sm[];
    uint32_t* Qs = sm + 2 * STAGE_WORDS;     // 8192 words (32KB) Q fragments

    const int qt   = (int)gridDim.x - 1 - (int)blockIdx.x;
    const int bh   = blockIdx.y;
    const int b    = bh >> 4;
    const int h    = bh & 15;
    const int tid  = threadIdx.x;
    const int lane = tid & 31;
    const int warp = tid >> 5;       // 0..3
    const int g    = lane >> 2;
    const int t    = lane & 3;

    const int wq0 = qt * 128 + warp * 32;
    const size_t base = ((size_t)b * SEQ_LEN) * D_MODEL + h * D_HEAD;
    const uint32_t* tile_base = KVP + (size_t)bh * NT64 * STAGE_WORDS;
    const uint32_t sm_addr = (uint32_t)__cvta_generic_to_shared(sm);
    const int nkt = 2 * qt + 2;

    // Q fragments -> per-warp SMEM region (written and read by same thread:
    // no barrier needed).
    #pragma unroll
    for (int mi = 0; mi < 2; mi++) {
        const int row0 = wq0 + mi * 16 + g, row1 = row0 + 8;
        #pragma unroll
        for (int kd = 0; kd < 8; kd++) {
            int c0 = kd * 8 + t, c1 = c0 + 4;
            uint4 qv;
            qv.x = f2tf32(Q[base + (size_t)row0 * D_MODEL + c0] * 0.125f);
            qv.y = f2tf32(Q[base + (size_t)row1 * D_MODEL + c0] * 0.125f);
            qv.z = f2tf32(Q[base + (size_t)row0 * D_MODEL + c1] * 0.125f);
            qv.w = f2tf32(Q[base + (size_t)row1 * D_MODEL + c1] * 0.125f);
            *reinterpret_cast<uint4*>(
                Qs + (size_t)(((warp * 2 + mi) * 8 + kd) * 32 + lane) * 4) = qv;
        }
    }

    float oc[2][8][4];
    #pragma unroll
    for (int mi = 0; mi < 2; mi++)
        #pragma unroll
        for (int nv = 0; nv < 8; nv++)
            #pragma unroll
            for (int r = 0; r < 4; r++) oc[mi][nv][r] = 0.0f;

    float mm[2][2], ll[2][2];
    #pragma unroll
    for (int mi = 0; mi < 2; mi++) {
        mm[mi][0] = -1.0e30f; mm[mi][1] = -1.0e30f;
        ll[mi][0] = 0.0f;     ll[mi][1] = 0.0f;
    }

    // 32KB linear copy per tile: 16 x (128 threads x 16B). 2-stage ring.
    auto issue_tile = [&](int kt) {
        if (kt < nkt) {
            const uint32_t* src = tile_base + (size_t)kt * STAGE_WORDS + tid * 4;
            uint32_t dst = sm_addr + ((kt & 1) * STAGE_WORDS + tid * 4) * 4;
            #pragma unroll
            for (int c = 0; c < 16; c++) {
                asm volatile("cp.async.cg.shared.global [%0], [%1], 16;\n"
                             :: "r"(dst + c * 2048), "l"(src + c * 512));
            }
        }
        asm volatile("cp.async.commit_group;\n");
    };

    issue_tile(0);
    issue_tile(1);

    const int src0 = (lane & ~3) | (t >> 1);
    const int src1 = src0 + 2;
    const bool odd = (t & 1);

    for (int kt = 0; kt < nkt; kt++) {
        asm volatile("cp.async.wait_group 1;\n");
        __syncthreads();

        const uint2* KhiS = reinterpret_cast<const uint2*>(sm + (kt & 1) * STAGE_WORDS);
        const uint2* VhiS = KhiS + 2048;
        const int k0 = kt * 64;

        if (k0 <= wq0 + 31) {
            // ---- S = QK^T: Q frags from SMEM, one K LDS feeds both m-tiles
            float sc[2][8][4];
            #pragma unroll
            for (int mi = 0; mi < 2; mi++)
                #pragma unroll
                for (int nt = 0; nt < 8; nt++)
                    #pragma unroll
                    for (int r = 0; r < 4; r++) sc[mi][nt][r] = 0.0f;

            #pragma unroll
            for (int kd = 0; kd < 8; kd++) {
                uint32_t q0[4], q1[4];
                *reinterpret_cast<uint4*>(q0) = *reinterpret_cast<const uint4*>(
                    Qs + (size_t)(((warp * 2 + 0) * 8 + kd) * 32 + lane) * 4);
                *reinterpret_cast<uint4*>(q1) = *reinterpret_cast<const uint4*>(
                    Qs + (size_t)(((warp * 2 + 1) * 8 + kd) * 32 + lane) * 4);
                #pragma unroll
                for (int nt = 0; nt < 8; nt++) {
                    uint2 bh2 = KhiS[(kd * 8 + nt) * 32 + lane];
                    mma_tf32(sc[0][nt], q0, bh2.x, bh2.y);
                    mma_tf32(sc[1][nt], q1, bh2.x, bh2.y);
                }
            }

            // ---- causal mask ----
            if (k0 + 63 > wq0) {
                #pragma unroll
                for (int mi = 0; mi < 2; mi++) {
                    const int row0 = wq0 + mi * 16 + g, row1 = row0 + 8;
                    #pragma unroll
                    for (int nt = 0; nt < 8; nt++) {
                        int col = k0 + nt * 8 + 2 * t;
                        if (col     > row0) sc[mi][nt][0] = -1.0e30f;
                        if (col + 1 > row0) sc[mi][nt][1] = -1.0e30f;
                        if (col     > row1) sc[mi][nt][2] = -1.0e30f;
                        if (col + 1 > row1) sc[mi][nt][3] = -1.0e30f;
                    }
                }
            }

            // ---- online softmax (per m-tile) ----
            #pragma unroll
            for (int mi = 0; mi < 2; mi++) {
                float mt0 = sc[mi][0][0], mt1 = sc[mi][0][2];
                #pragma unroll
                for (int nt = 0; nt < 8; nt++) {
                    mt0 = fmaxf(mt0, fmaxf(sc[mi][nt][0], sc[mi][nt][1]));
                    mt1 = fmaxf(mt1, fmaxf(sc[mi][nt][2], sc[mi][nt][3]));
                }
                #pragma unroll
                for (int w = 1; w < 4; w <<= 1) {
                    mt0 = fmaxf(mt0, __shfl_xor_sync(0xffffffff, mt0, w));
                    mt1 = fmaxf(mt1, __shfl_xor_sync(0xffffffff, mt1, w));
                }
                float mn0 = fmaxf(mm[mi][0], mt0), mn1 = fmaxf(mm[mi][1], mt1);
                float cr0 = __expf(mm[mi][0] - mn0), cr1 = __expf(mm[mi][1] - mn1);
                mm[mi][0] = mn0; mm[mi][1] = mn1;
                ll[mi][0] *= cr0; ll[mi][1] *= cr1;
                #pragma unroll
                for (int nv = 0; nv < 8; nv++) {
                    oc[mi][nv][0] *= cr0; oc[mi][nv][1] *= cr0;
                    oc[mi][nv][2] *= cr1; oc[mi][nv][3] *= cr1;
                }
            }

            // ---- per key-group: exp -> transpose -> PV (shared V LDS) ----
            #pragma unroll
            for (int nt = 0; nt < 8; nt++) {
                uint32_t ph[2][4];
                #pragma unroll
                for (int mi = 0; mi < 2; mi++) {
                    float p0 = __expf(sc[mi][nt][0] - mm[mi][0]);
                    float p1 = __expf(sc[mi][nt][1] - mm[mi][0]);
                    float p2 = __expf(sc[mi][nt][2] - mm[mi][1]);
                    float p3 = __expf(sc[mi][nt][3] - mm[mi][1]);
                    ll[mi][0] += p0 + p1;
                    ll[mi][1] += p2 + p3;

                    float t00 = __shfl_sync(0xffffffff, p0, src0);
                    float t01 = __shfl_sync(0xffffffff, p1, src0);
                    float a0f = odd ? t01 : t00;
                    float t10 = __shfl_sync(0xffffffff, p2, src0);
                    float t11 = __shfl_sync(0xffffffff, p3, src0);
                    float a1f = odd ? t11 : t10;
                    float t20 = __shfl_sync(0xffffffff, p0, src1);
                    float t21 = __shfl_sync(0xffffffff, p1, src1);
                    float a2f = odd ? t21 : t20;
                    float t30 = __shfl_sync(0xffffffff, p2, src1);
                    float t31 = __shfl_sync(0xffffffff, p3, src1);
                    float a3f = odd ? t31 : t30;

                    ph[mi][0] = f2tf32(a0f);
                    ph[mi][1] = f2tf32(a1f);
                    ph[mi][2] = f2tf32(a2f);
                    ph[mi][3] = f2tf32(a3f);
                }

                #pragma unroll
                for (int nv = 0; nv < 8; nv++) {
                    uint2 vh2 = VhiS[(nt * 8 + nv) * 32 + lane];
                    mma_tf32(oc[0][nv], ph[0], vh2.x, vh2.y);
                    mma_tf32(oc[1][nv], ph[1], vh2.x, vh2.y);
                }
            }
        }

        // All warps done reading stage (kt&1) before refilling it.
        __syncthreads();
        issue_tile(kt + 2);
    }

    // ---- finalize: normalize, transpose to A-frag order, store packed ----
    #pragma unroll
    for (int mi = 0; mi < 2; mi++) {
        #pragma unroll
        for (int w = 1; w < 4; w <<= 1) {
            ll[mi][0] += __shfl_xor_sync(0xffffffff, ll[mi][0], w);
            ll[mi][1] += __shfl_xor_sync(0xffffffff, ll[mi][1], w);
        }
    }
    const int rb = b * (SEQ_LEN / 128) + qt;
    uint32_t* ablk0 = APK + ((size_t)rb * KT_N + h * 2) * 4096;

    #pragma unroll
    for (int mi = 0; mi < 2; mi++) {
        const float inv0 = 1.0f / ll[mi][0], inv1 = 1.0f / ll[mi][1];
        const int mt = warp * 2 + mi;    // m-tile index 0..7
        #pragma unroll
        for (int nv = 0; nv < 8; nv++) {
            float p0 = oc[mi][nv][0] * inv0, p1 = oc[mi][nv][1] * inv0;
            float p2 = oc[mi][nv][2] * inv1, p3 = oc[mi][nv][3] * inv1;
            float t00 = __shfl_sync(0xffffffff, p0, src0);
            float t01 = __shfl_sync(0xffffffff, p1, src0);
            float a0 = odd ? t01 : t00;
            float t10 = __shfl_sync(0xffffffff, p2, src0);
            float t11 = __shfl_sync(0xffffffff, p3, src0);
            float a1 = odd ? t11 : t10;
            float t20 = __shfl_sync(0xffffffff, p0, src1);
            float t21 = __shfl_sync(0xffffffff, p1, src1);
            float a2 = odd ? t21 : t20;
            float t30 = __shfl_sync(0xffffffff, p2, src1);
            float t31 = __shfl_sync(0xffffffff, p3, src1);
            float a3 = odd ? t31 : t30;
            uint4 wv = make_uint4(f2tf32(a0), f2tf32(a1), f2tf32(a2), f2tf32(a3));
            uint32_t* dst = ablk0 + (size_t)(nv >> 2) * 4096
                                  + (size_t)(((nv & 3) * 8 + mt) * 32 + lane) * 4;
            *reinterpret_cast<uint4*>(dst) = wv;
        }
    }
}

// ---------------------------------------------------------------------------
// Launch: pack prepass -> fused QKV GEMM (K/V packed directly) -> attn
//         (packed O) -> output GEMM.
// ---------------------------------------------------------------------------
extern "C" void kernel_launch(void* const* d_in, const int* in_sizes, int n_in,
                              void* d_out, int out_size)
{
    const float* x  = (const float*)d_in[0];
    const float* Wq = (const float*)d_in[1];
    const float* bq = (const float*)d_in[2];
    const float* Wk = (const float*)d_in[3];
    const float* bk = (const float*)d_in[4];
    const float* Wv = (const float*)d_in[5];
    const float* bv = (const float*)d_in[6];
    const float* Wo = (const float*)d_in[7];
    const float* bo = (const float*)d_in[8];
    float* out = (float*)d_out;

    const int M = in_sizes[0] / D_MODEL;   // 4096
    const int B = M / SEQ_LEN;             // 2

    float* Qp;
    uint32_t *APKp, *WPKp, *KVPp;
    cudaGetSymbolAddress((void**)&Qp, g_Q);
    cudaGetSymbolAddress((void**)&APKp, g_APK);
    cudaGetSymbolAddress((void**)&WPKp, g_WPK);
    cudaGetSymbolAddress((void**)&KVPp, g_KVP);

    static bool attr_set = false;
    if (!attr_set) {
        cudaFuncSetAttribute(attn_mma_kernel,
                             cudaFuncAttributeMaxDynamicSharedMemorySize,
                             3 * STAGE_WORDS * 4);   // 2 stages + Q region
        cudaFuncSetAttribute(gemm_qkv_kernel,
                             cudaFuncAttributeMaxDynamicSharedMemorySize,
                             3 * GW * 4);
        cudaFuncSetAttribute(gemm_out_kernel,
                             cudaFuncAttributeMaxDynamicSharedMemorySize,
                             3 * GW * 4);
        attr_set = true;
    }

    const int gemm_smem = 3 * GW * 4;             // 98304 B
    dim3 qkv_grid(8, M / 128, 3);                 // (8, 32, 3)
    dim3 gemm_grid(8, M / 128);                   // (8, 32)
    dim3 pa_grid(KT_N, M / 128);                  // (32, 32)
    dim3 pw_grid(KT_N, 8, 4);                     // (32, 8, 4)

    // Pre-pass: fragment-pack A (x) and all 4 weight matrices.
    pack_a_kernel<<<pa_grid, 256>>>(x, APKp);
    pack_w_kernel<<<pw_grid, 256>>>(Wq, Wk, Wv, Wo, WPKp);

    // Fused QKV projections; K and V written directly in packed KV layout.
    gemm_qkv_kernel<<<qkv_grid, 256, gemm_smem>>>(APKp, WPKp, bq, bk, bv, Qp, KVPp);

    // Attention: 128 threads, warp = 32 queries (2 m-tiles), Q in SMEM.
    dim3 attn_grid(SEQ_LEN / 128, B * NUM_HEADS); // (16, 32)
    attn_mma_kernel<<<attn_grid, 128, 3 * STAGE_WORDS * 4>>>(Qp, KVPp, APKp);

    // Output projection.
    gemm_out_kernel<<<gemm_grid, 256, gemm_smem>>>(APKp, WPKp + 3 * WSTRIDE, bo, out);
}